// round 16
// baseline (speedup 1.0000x reference)
#include <cuda_runtime.h>

#define NN 50000      // nodes
#define NE 50000      // hyperedges
#define EE 320000     // incidences
#define DD 256        // feature dim
#define ELLS 48       // padded ELL stride (max degree ~25 for Poisson(6.4); P(>=48) ~ 1e-18)

// ---------------- scratch (device globals; no allocation allowed) -------------
__device__ float g_xw[NN * DD];      // X @ W^T
__device__ float g_edge[NE * DD];    // hyperedge features
__device__ float g_h1[NN * DD];      // layer-1 output
__device__ int g_deg_n[NN];
__device__ int g_deg_e[NE];
__device__ int g_ell_he[NE * ELLS];    // per hyperedge: incident node indices
__device__ int g_ell_node[NN * ELLS];  // per node: incident hyperedge indices
__device__ int g_is_i32;

// ---------------- helpers ------------------------------------------------------
__device__ __forceinline__ int ld_idx(const void* p, long long e, int is32) {
    if (is32) return ((const int*)p)[e];
    return (int)(((const long long*)p)[e]);
}

// ---------------- init / dtype detect ------------------------------------------
__global__ void init_k() {
    int i = blockIdx.x * blockDim.x + threadIdx.x;
    if (i < NN) { g_deg_n[i] = 0; g_deg_e[i] = 0; }
    if (i == 0) g_is_i32 = 0;
}

// Genuine int64 indices are all < 50000. If the buffer actually holds int32,
// each u64 word packs two values and is >= 2^32 unless the high int32 is 0.
__global__ void detect_k(const unsigned long long* __restrict__ p) {
    unsigned long long v = p[threadIdx.x];
    unsigned int bad = __ballot_sync(0xffffffffu, v > 49999ULL);
    if ((threadIdx.x & 31) == 0 && bad) atomicOr(&g_is_i32, 1);
}

// ---------------- fused ELL build -----------------------------------------------
__global__ void build_k(const void* __restrict__ hei) {
    int e = blockIdx.x * blockDim.x + threadIdx.x;
    if (e >= EE) return;
    int f = g_is_i32;
    int s = ld_idx(hei, e, f);        // row 0: node index
    int h = ld_idx(hei, EE + e, f);   // row 1: hyperedge index
    int se = atomicAdd(&g_deg_e[h], 1);
    if (se < ELLS) g_ell_he[h * ELLS + se] = s;
    int sn = atomicAdd(&g_deg_n[s], 1);
    if (sn < ELLS) g_ell_node[s * ELLS + sn] = h;
}

// ---------------- TF32 tensor-core GEMM: C = A @ W^T  (3xTF32, split hoisted) ---
// Block tile 128x128, BK=16, 256 threads (8 warps of 32x64 warp tiles).
// hi/lo TF32 splits are computed ONCE during smem staging; the inner loop is
// pure LDS + MMA (no cvt on the critical path).
#define BM 128
#define BN 128
#define BK 16
#define LDSS (BK + 4)   // 20 words/row: (20*g + t) mod 32 covers all banks -> conflict-free

__device__ __forceinline__ void tf32_split(float v, unsigned& hi, unsigned& lo) {
    unsigned h;
    asm("cvt.rna.tf32.f32 %0, %1;" : "=r"(h) : "f"(v));
    float lf = v - __uint_as_float(h);
    unsigned l;
    asm("cvt.rna.tf32.f32 %0, %1;" : "=r"(l) : "f"(lf));
    hi = h; lo = l;
}

__device__ __forceinline__ void split4(float4 v, uint4& hi, uint4& lo) {
    tf32_split(v.x, hi.x, lo.x);
    tf32_split(v.y, hi.y, lo.y);
    tf32_split(v.z, hi.z, lo.z);
    tf32_split(v.w, hi.w, lo.w);
}

__device__ __forceinline__ void mma_tf32(float c[4], const unsigned a[4], const unsigned b[2]) {
    asm volatile(
        "mma.sync.aligned.m16n8k8.row.col.f32.tf32.tf32.f32 "
        "{%0,%1,%2,%3}, {%4,%5,%6,%7}, {%8,%9}, {%0,%1,%2,%3};\n"
        : "+f"(c[0]), "+f"(c[1]), "+f"(c[2]), "+f"(c[3])
        : "r"(a[0]), "r"(a[1]), "r"(a[2]), "r"(a[3]), "r"(b[0]), "r"(b[1]));
}

__global__ __launch_bounds__(256, 2) void gemm_tf32_k(const float* __restrict__ Aext,
                                                      const float* __restrict__ W,
                                                      int useH1) {
    const float* __restrict__ A = useH1 ? (const float*)g_h1 : Aext;
    float* __restrict__ C = g_xw;

    __shared__ unsigned As_hi[BM * LDSS];   // 10 KB each, 40 KB total
    __shared__ unsigned As_lo[BM * LDSS];
    __shared__ unsigned Bs_hi[BN * LDSS];
    __shared__ unsigned Bs_lo[BN * LDSS];

    const int bm = blockIdx.x * BM;
    const int bn = blockIdx.y * BN;
    const int tid = threadIdx.x;
    const int warp = tid >> 5, lane = tid & 31;
    const int wm = warp >> 1;          // 0..3 -> M offset wm*32
    const int wn = warp & 1;           // 0..1 -> N offset wn*64
    const int grp = lane >> 2, tig = lane & 3;

    float cacc[2][8][4];
#pragma unroll
    for (int mt = 0; mt < 2; mt++)
#pragma unroll
        for (int nt = 0; nt < 8; nt++)
#pragma unroll
            for (int e = 0; e < 4; e++) cacc[mt][nt][e] = 0.f;

    // staging coordinates: 512 float4 per matrix per chunk, 2 per thread
    const int f0 = tid, f1 = tid + 256;
    const int r0s = f0 >> 2, c0s = (f0 & 3) << 2;
    const int r1s = f1 >> 2, c1s = (f1 & 3) << 2;

    float4 pa[2], pb[2];

    // ---- load + split + store chunk 0 ----
    pa[0] = (bm + r0s < NN) ? *(const float4*)&A[(size_t)(bm + r0s) * DD + c0s]
                            : make_float4(0.f, 0.f, 0.f, 0.f);
    pa[1] = (bm + r1s < NN) ? *(const float4*)&A[(size_t)(bm + r1s) * DD + c1s]
                            : make_float4(0.f, 0.f, 0.f, 0.f);
    pb[0] = *(const float4*)&W[(size_t)(bn + r0s) * DD + c0s];
    pb[1] = *(const float4*)&W[(size_t)(bn + r1s) * DD + c1s];
    {
        uint4 hi, lo;
        split4(pa[0], hi, lo);
        *(uint4*)&As_hi[r0s * LDSS + c0s] = hi; *(uint4*)&As_lo[r0s * LDSS + c0s] = lo;
        split4(pa[1], hi, lo);
        *(uint4*)&As_hi[r1s * LDSS + c1s] = hi; *(uint4*)&As_lo[r1s * LDSS + c1s] = lo;
        split4(pb[0], hi, lo);
        *(uint4*)&Bs_hi[r0s * LDSS + c0s] = hi; *(uint4*)&Bs_lo[r0s * LDSS + c0s] = lo;
        split4(pb[1], hi, lo);
        *(uint4*)&Bs_hi[r1s * LDSS + c1s] = hi; *(uint4*)&Bs_lo[r1s * LDSS + c1s] = lo;
    }
    __syncthreads();

    for (int kb = 0; kb < DD; kb += BK) {
        // prefetch next chunk into registers (overlaps with MMA below)
        if (kb + BK < DD) {
            int ko = kb + BK;
            pa[0] = (bm + r0s < NN) ? *(const float4*)&A[(size_t)(bm + r0s) * DD + ko + c0s]
                                    : make_float4(0.f, 0.f, 0.f, 0.f);
            pa[1] = (bm + r1s < NN) ? *(const float4*)&A[(size_t)(bm + r1s) * DD + ko + c1s]
                                    : make_float4(0.f, 0.f, 0.f, 0.f);
            pb[0] = *(const float4*)&W[(size_t)(bn + r0s) * DD + ko + c0s];
            pb[1] = *(const float4*)&W[(size_t)(bn + r1s) * DD + ko + c1s];
        }

        // 2 k-steps of 8 on the resident chunk: pure LDS + MMA
#pragma unroll
        for (int ks = 0; ks < 2; ks++) {
            const int k0 = ks * 8;
            unsigned ahi[2][4], alo[2][4];
#pragma unroll
            for (int mt = 0; mt < 2; mt++) {
                int ra = wm * 32 + mt * 16 + grp;
                int base0 = ra * LDSS + k0 + tig;
                int base1 = (ra + 8) * LDSS + k0 + tig;
                ahi[mt][0] = As_hi[base0];     alo[mt][0] = As_lo[base0];
                ahi[mt][1] = As_hi[base1];     alo[mt][1] = As_lo[base1];
                ahi[mt][2] = As_hi[base0 + 4]; alo[mt][2] = As_lo[base0 + 4];
                ahi[mt][3] = As_hi[base1 + 4]; alo[mt][3] = As_lo[base1 + 4];
            }
#pragma unroll
            for (int nt = 0; nt < 8; nt++) {
                int nb = (wn * 64 + nt * 8 + grp) * LDSS + k0 + tig;
                unsigned bhi[2], blo[2];
                bhi[0] = Bs_hi[nb];     blo[0] = Bs_lo[nb];
                bhi[1] = Bs_hi[nb + 4]; blo[1] = Bs_lo[nb + 4];
#pragma unroll
                for (int mt = 0; mt < 2; mt++) {
                    mma_tf32(cacc[mt][nt], ahi[mt], blo);
                    mma_tf32(cacc[mt][nt], alo[mt], bhi);
                    mma_tf32(cacc[mt][nt], ahi[mt], bhi);
                }
            }
        }
        __syncthreads();
        if (kb + BK < DD) {
            uint4 hi, lo;
            split4(pa[0], hi, lo);
            *(uint4*)&As_hi[r0s * LDSS + c0s] = hi; *(uint4*)&As_lo[r0s * LDSS + c0s] = lo;
            split4(pa[1], hi, lo);
            *(uint4*)&As_hi[r1s * LDSS + c1s] = hi; *(uint4*)&As_lo[r1s * LDSS + c1s] = lo;
            split4(pb[0], hi, lo);
            *(uint4*)&Bs_hi[r0s * LDSS + c0s] = hi; *(uint4*)&Bs_lo[r0s * LDSS + c0s] = lo;
            split4(pb[1], hi, lo);
            *(uint4*)&Bs_hi[r1s * LDSS + c1s] = hi; *(uint4*)&Bs_lo[r1s * LDSS + c1s] = lo;
            __syncthreads();
        }
    }

    // ---- epilogue: store C ----
#pragma unroll
    for (int mt = 0; mt < 2; mt++) {
        int row0 = bm + wm * 32 + mt * 16 + grp;
#pragma unroll
        for (int nt = 0; nt < 8; nt++) {
            int col = bn + wn * 64 + nt * 8 + tig * 2;
            if (row0 < NN)
                *(float2*)&C[(size_t)row0 * DD + col] =
                    make_float2(cacc[mt][nt][0], cacc[mt][nt][1]);
            if (row0 + 8 < NN)
                *(float2*)&C[(size_t)(row0 + 8) * DD + col] =
                    make_float2(cacc[mt][nt][2], cacc[mt][nt][3]);
        }
    }
}

// ---------------- aggregation: hyperedge <- mean over incident nodes ------------
__global__ void edge_agg_k() {
    int gw = (blockIdx.x * blockDim.x + threadIdx.x) >> 5;
    int lane = threadIdx.x & 31;
    if (gw >= NE) return;
    int deg = g_deg_e[gw];
    if (deg > ELLS) deg = ELLS;
    float4 a0 = make_float4(0.f, 0.f, 0.f, 0.f);
    float4 a1 = a0;
    const int* __restrict__ idx = g_ell_he + (size_t)gw * ELLS;
    for (int k = 0; k < deg; k++) {
        int n = idx[k];
        const float4* row = (const float4*)(g_xw + (size_t)n * DD);
        float4 v0 = __ldg(&row[lane]);
        float4 v1 = __ldg(&row[lane + 32]);
        a0.x += v0.x; a0.y += v0.y; a0.z += v0.z; a0.w += v0.w;
        a1.x += v1.x; a1.y += v1.y; a1.z += v1.z; a1.w += v1.w;
    }
    float inv = (deg > 0) ? 1.f / (float)deg : 0.f;
    a0.x *= inv; a0.y *= inv; a0.z *= inv; a0.w *= inv;
    a1.x *= inv; a1.y *= inv; a1.z *= inv; a1.w *= inv;
    float4* orow = (float4*)(g_edge + (size_t)gw * DD);
    orow[lane] = a0;
    orow[lane + 32] = a1;
}

// ---------------- aggregation: node <- mean over incident hyperedges + epilogue -
__global__ void node_agg_k(const float* __restrict__ bias,
                           const float* __restrict__ prelu_a,
                           const float* __restrict__ residual,
                           float* __restrict__ out_ext,
                           int layer2) {
    int gw = (blockIdx.x * blockDim.x + threadIdx.x) >> 5;
    int lane = threadIdx.x & 31;
    if (gw >= NN) return;
    int deg = g_deg_n[gw];
    if (deg > ELLS) deg = ELLS;
    float4 a0 = make_float4(0.f, 0.f, 0.f, 0.f);
    float4 a1 = a0;
    const int* __restrict__ idx = g_ell_node + (size_t)gw * ELLS;
    for (int k = 0; k < deg; k++) {
        int h = idx[k];
        const float4* row = (const float4*)(g_edge + (size_t)h * DD);
        float4 v0 = __ldg(&row[lane]);
        float4 v1 = __ldg(&row[lane + 32]);
        a0.x += v0.x; a0.y += v0.y; a0.z += v0.z; a0.w += v0.w;
        a1.x += v1.x; a1.y += v1.y; a1.z += v1.z; a1.w += v1.w;
    }
    float inv = (deg > 0) ? 1.f / (float)deg : 0.f;
    float a = __ldg(prelu_a);
    float4 b0 = *(const float4*)&bias[lane * 4];
    float4 b1 = *(const float4*)&bias[128 + lane * 4];

    float4 r0, r1;
    r0.x = a0.x * inv + b0.x; r0.y = a0.y * inv + b0.y;
    r0.z = a0.z * inv + b0.z; r0.w = a0.w * inv + b0.w;
    r1.x = a1.x * inv + b1.x; r1.y = a1.y * inv + b1.y;
    r1.z = a1.z * inv + b1.z; r1.w = a1.w * inv + b1.w;

    if (layer2) {
        const float4* xr = (const float4*)(residual + (size_t)gw * DD);
        float4 x0 = __ldg(&xr[lane]);
        float4 x1 = __ldg(&xr[lane + 32]);
        r0.x += x0.x; r0.y += x0.y; r0.z += x0.z; r0.w += x0.w;
        r1.x += x1.x; r1.y += x1.y; r1.z += x1.z; r1.w += x1.w;
    }

    r0.x = (r0.x >= 0.f) ? r0.x : a * r0.x;
    r0.y = (r0.y >= 0.f) ? r0.y : a * r0.y;
    r0.z = (r0.z >= 0.f) ? r0.z : a * r0.z;
    r0.w = (r0.w >= 0.f) ? r0.w : a * r0.w;
    r1.x = (r1.x >= 0.f) ? r1.x : a * r1.x;
    r1.y = (r1.y >= 0.f) ? r1.y : a * r1.y;
    r1.z = (r1.z >= 0.f) ? r1.z : a * r1.z;
    r1.w = (r1.w >= 0.f) ? r1.w : a * r1.w;

    float* out = layer2 ? out_ext : (float*)g_h1;
    float4* orow = (float4*)(out + (size_t)gw * DD);
    orow[lane] = r0;
    orow[lane + 32] = r1;
}

// ---------------- launch ---------------------------------------------------------
extern "C" void kernel_launch(void* const* d_in, const int* in_sizes, int n_in,
                              void* d_out, int out_size) {
    const float* x   = (const float*)d_in[0];
    const float* W1  = (const float*)d_in[1];
    const float* b1  = (const float*)d_in[2];
    const float* W2  = (const float*)d_in[3];
    const float* b2  = (const float*)d_in[4];
    const float* pa  = (const float*)d_in[5];
    const void*  hei = d_in[6];
    float* out = (float*)d_out;

    // ELL incidence build (recomputed every launch; deterministic)
    init_k<<<(NN + 255) / 256, 256>>>();
    detect_k<<<1, 1024>>>((const unsigned long long*)hei);
    build_k<<<(EE + 255) / 256, 256>>>(hei);

    dim3 gg((NN + BM - 1) / BM, DD / BN);
    int agg_blocks = (NN * 32 + 255) / 256;   // one warp per row, 8 warps/block

    // layer 1: xw = x @ W1^T ; edge agg ; node agg (+b1, prelu) -> g_h1
    gemm_tf32_k<<<gg, 256>>>(x, W1, 0);
    edge_agg_k<<<agg_blocks, 256>>>();
    node_agg_k<<<agg_blocks, 256>>>(b1, pa, nullptr, nullptr, 0);

    // layer 2: xw = h1 @ W2^T ; edge agg ; node agg (+b2, +x residual, prelu)
    gemm_tf32_k<<<gg, 256>>>(x, W2, 1);
    edge_agg_k<<<agg_blocks, 256>>>();
    node_agg_k<<<agg_blocks, 256>>>(b2, pa, x, out, 1);
}

// round 17
// speedup vs baseline: 1.3760x; 1.3760x over previous
#include <cuda_runtime.h>
#include <cuda_bf16.h>

#define NN 50000      // nodes
#define NE 50000      // hyperedges
#define EE 320000     // incidences
#define DD 256        // feature dim
#define ELLS 48       // padded ELL stride (max degree ~25 for Poisson(6.4); P(>=48) ~ 1e-18)

// ---------------- scratch (device globals; no allocation allowed) -------------
__device__ float g_xw[NN * DD];      // X @ W^T
__device__ float g_edge[NE * DD];    // hyperedge features
__device__ float g_h1[NN * DD];      // layer-1 output
__device__ int g_deg_n[NN];
__device__ int g_deg_e[NE];
__device__ int g_ell_he[NE * ELLS];    // per hyperedge: incident node indices
__device__ int g_ell_node[NN * ELLS];  // per node: incident hyperedge indices
__device__ int g_is_i32;

// ---------------- helpers ------------------------------------------------------
__device__ __forceinline__ int ld_idx(const void* p, long long e, int is32) {
    if (is32) return ((const int*)p)[e];
    return (int)(((const long long*)p)[e]);
}

// ---------------- init / dtype detect ------------------------------------------
__global__ void init_k() {
    int i = blockIdx.x * blockDim.x + threadIdx.x;
    if (i < NN) { g_deg_n[i] = 0; g_deg_e[i] = 0; }
    if (i == 0) g_is_i32 = 0;
}

// Genuine int64 indices are all < 50000. If the buffer actually holds int32,
// each u64 word packs two values and is >= 2^32 unless the high int32 is 0.
__global__ void detect_k(const unsigned long long* __restrict__ p) {
    unsigned long long v = p[threadIdx.x];
    unsigned int bad = __ballot_sync(0xffffffffu, v > 49999ULL);
    if ((threadIdx.x & 31) == 0 && bad) atomicOr(&g_is_i32, 1);
}

// ---------------- fused ELL build -----------------------------------------------
__global__ void build_k(const void* __restrict__ hei) {
    int e = blockIdx.x * blockDim.x + threadIdx.x;
    if (e >= EE) return;
    int f = g_is_i32;
    int s = ld_idx(hei, e, f);        // row 0: node index
    int h = ld_idx(hei, EE + e, f);   // row 1: hyperedge index
    int se = atomicAdd(&g_deg_e[h], 1);
    if (se < ELLS) g_ell_he[h * ELLS + se] = s;
    int sn = atomicAdd(&g_deg_n[s], 1);
    if (sn < ELLS) g_ell_node[s * ELLS + sn] = h;
}

// ---------------- BF16 split tensor-core GEMM: C = A @ W^T ----------------------
// fp32 emulated as hi+lo bf16 (16 mantissa bits): C = Ahi*Bhi + Ahi*Blo + Alo*Bhi.
// Dropped Alo*Blo term ~2^-18 rel -> global rel err ~1e-5 (budget 1e-3).
// mma.m16n8k16 consumes K=16/instr: half the MMA count AND half the smem bytes
// of the 3xTF32 path. Block tile 128x128, BK=16, 256 threads, 32x64 warp tiles.
#define BM 128
#define BN 128
#define BK 16
// packed k-pair words per row = BK/2 = 8; pad to 12 for conflict-free frag LDS:
// bank(grp*12 + tig) distinct for all 32 lanes.
#define LDSW 12

// pack two consecutive-k fp32 into one bf16x2 word (lo half = even k), and
// the residuals into a second bf16x2 word.
__device__ __forceinline__ void split_pair(float v0, float v1, unsigned& hi, unsigned& lo) {
    unsigned h;
    asm("cvt.rn.bf16x2.f32 %0, %1, %2;" : "=r"(h) : "f"(v1), "f"(v0));  // {hi16:v1, lo16:v0}
    float h0 = __uint_as_float(h << 16);
    float h1 = __uint_as_float(h & 0xffff0000u);
    float r0 = v0 - h0;
    float r1 = v1 - h1;
    unsigned l;
    asm("cvt.rn.bf16x2.f32 %0, %1, %2;" : "=r"(l) : "f"(r1), "f"(r0));
    hi = h; lo = l;
}

__device__ __forceinline__ void split4(float4 v, unsigned hi[2], unsigned lo[2]) {
    split_pair(v.x, v.y, hi[0], lo[0]);
    split_pair(v.z, v.w, hi[1], lo[1]);
}

__device__ __forceinline__ void mma_bf16(float c[4], const unsigned a[4], const unsigned b[2]) {
    asm volatile(
        "mma.sync.aligned.m16n8k16.row.col.f32.bf16.bf16.f32 "
        "{%0,%1,%2,%3}, {%4,%5,%6,%7}, {%8,%9}, {%0,%1,%2,%3};\n"
        : "+f"(c[0]), "+f"(c[1]), "+f"(c[2]), "+f"(c[3])
        : "r"(a[0]), "r"(a[1]), "r"(a[2]), "r"(a[3]), "r"(b[0]), "r"(b[1]));
}

__global__ __launch_bounds__(256, 2) void gemm_bf16_k(const float* __restrict__ Aext,
                                                      const float* __restrict__ W,
                                                      int useH1) {
    const float* __restrict__ A = useH1 ? (const float*)g_h1 : Aext;
    float* __restrict__ C = g_xw;

    __shared__ unsigned As_hi[BM * LDSW];   // 6 KB each, 24 KB total
    __shared__ unsigned As_lo[BM * LDSW];
    __shared__ unsigned Bs_hi[BN * LDSW];
    __shared__ unsigned Bs_lo[BN * LDSW];

    const int bm = blockIdx.x * BM;
    const int bn = blockIdx.y * BN;
    const int tid = threadIdx.x;
    const int warp = tid >> 5, lane = tid & 31;
    const int wm = warp >> 1;          // 0..3 -> M offset wm*32
    const int wn = warp & 1;           // 0..1 -> N offset wn*64
    const int grp = lane >> 2, tig = lane & 3;

    float cacc[2][8][4];
#pragma unroll
    for (int mt = 0; mt < 2; mt++)
#pragma unroll
        for (int nt = 0; nt < 8; nt++)
#pragma unroll
            for (int e = 0; e < 4; e++) cacc[mt][nt][e] = 0.f;

    // staging coordinates: 512 float4 per matrix per chunk (128 rows x 16 k),
    // 2 float4 per thread. row = f>>2, k-offset = (f&3)*4.
    const int f0 = tid, f1 = tid + 256;
    const int r0s = f0 >> 2, c0s = (f0 & 3) << 2;
    const int r1s = f1 >> 2, c1s = (f1 & 3) << 2;

    float4 pa[2], pb[2];

    // ---- load + split + store chunk 0 ----
    pa[0] = (bm + r0s < NN) ? *(const float4*)&A[(size_t)(bm + r0s) * DD + c0s]
                            : make_float4(0.f, 0.f, 0.f, 0.f);
    pa[1] = (bm + r1s < NN) ? *(const float4*)&A[(size_t)(bm + r1s) * DD + c1s]
                            : make_float4(0.f, 0.f, 0.f, 0.f);
    pb[0] = *(const float4*)&W[(size_t)(bn + r0s) * DD + c0s];
    pb[1] = *(const float4*)&W[(size_t)(bn + r1s) * DD + c1s];
    {
        unsigned hi[2], lo[2];
        split4(pa[0], hi, lo);
        *(uint2*)&As_hi[r0s * LDSW + (c0s >> 1)] = make_uint2(hi[0], hi[1]);
        *(uint2*)&As_lo[r0s * LDSW + (c0s >> 1)] = make_uint2(lo[0], lo[1]);
        split4(pa[1], hi, lo);
        *(uint2*)&As_hi[r1s * LDSW + (c1s >> 1)] = make_uint2(hi[0], hi[1]);
        *(uint2*)&As_lo[r1s * LDSW + (c1s >> 1)] = make_uint2(lo[0], lo[1]);
        split4(pb[0], hi, lo);
        *(uint2*)&Bs_hi[r0s * LDSW + (c0s >> 1)] = make_uint2(hi[0], hi[1]);
        *(uint2*)&Bs_lo[r0s * LDSW + (c0s >> 1)] = make_uint2(lo[0], lo[1]);
        split4(pb[1], hi, lo);
        *(uint2*)&Bs_hi[r1s * LDSW + (c1s >> 1)] = make_uint2(hi[0], hi[1]);
        *(uint2*)&Bs_lo[r1s * LDSW + (c1s >> 1)] = make_uint2(lo[0], lo[1]);
    }
    __syncthreads();

    for (int kb = 0; kb < DD; kb += BK) {
        // prefetch next chunk into registers (overlaps with MMA below)
        if (kb + BK < DD) {
            int ko = kb + BK;
            pa[0] = (bm + r0s < NN) ? *(const float4*)&A[(size_t)(bm + r0s) * DD + ko + c0s]
                                    : make_float4(0.f, 0.f, 0.f, 0.f);
            pa[1] = (bm + r1s < NN) ? *(const float4*)&A[(size_t)(bm + r1s) * DD + ko + c1s]
                                    : make_float4(0.f, 0.f, 0.f, 0.f);
            pb[0] = *(const float4*)&W[(size_t)(bn + r0s) * DD + ko + c0s];
            pb[1] = *(const float4*)&W[(size_t)(bn + r1s) * DD + ko + c1s];
        }

        // one m16n8k16 k-step on the resident chunk: pure LDS + MMA
        {
            unsigned ahi[2][4], alo[2][4];
#pragma unroll
            for (int mt = 0; mt < 2; mt++) {
                int ra = wm * 32 + mt * 16 + grp;
                int b0 = ra * LDSW + tig;
                int b1 = (ra + 8) * LDSW + tig;
                ahi[mt][0] = As_hi[b0];     alo[mt][0] = As_lo[b0];       // k0..7
                ahi[mt][1] = As_hi[b1];     alo[mt][1] = As_lo[b1];
                ahi[mt][2] = As_hi[b0 + 4]; alo[mt][2] = As_lo[b0 + 4];   // k8..15
                ahi[mt][3] = As_hi[b1 + 4]; alo[mt][3] = As_lo[b1 + 4];
            }
#pragma unroll
            for (int nt = 0; nt < 8; nt++) {
                int nb = (wn * 64 + nt * 8 + grp) * LDSW + tig;
                unsigned bhi[2], blo[2];
                bhi[0] = Bs_hi[nb];     blo[0] = Bs_lo[nb];
                bhi[1] = Bs_hi[nb + 4]; blo[1] = Bs_lo[nb + 4];
#pragma unroll
                for (int mt = 0; mt < 2; mt++) {
                    mma_bf16(cacc[mt][nt], ahi[mt], blo);
                    mma_bf16(cacc[mt][nt], alo[mt], bhi);
                    mma_bf16(cacc[mt][nt], ahi[mt], bhi);
                }
            }
        }
        __syncthreads();
        if (kb + BK < DD) {
            unsigned hi[2], lo[2];
            split4(pa[0], hi, lo);
            *(uint2*)&As_hi[r0s * LDSW + (c0s >> 1)] = make_uint2(hi[0], hi[1]);
            *(uint2*)&As_lo[r0s * LDSW + (c0s >> 1)] = make_uint2(lo[0], lo[1]);
            split4(pa[1], hi, lo);
            *(uint2*)&As_hi[r1s * LDSW + (c1s >> 1)] = make_uint2(hi[0], hi[1]);
            *(uint2*)&As_lo[r1s * LDSW + (c1s >> 1)] = make_uint2(lo[0], lo[1]);
            split4(pb[0], hi, lo);
            *(uint2*)&Bs_hi[r0s * LDSW + (c0s >> 1)] = make_uint2(hi[0], hi[1]);
            *(uint2*)&Bs_lo[r0s * LDSW + (c0s >> 1)] = make_uint2(lo[0], lo[1]);
            split4(pb[1], hi, lo);
            *(uint2*)&Bs_hi[r1s * LDSW + (c1s >> 1)] = make_uint2(hi[0], hi[1]);
            *(uint2*)&Bs_lo[r1s * LDSW + (c1s >> 1)] = make_uint2(lo[0], lo[1]);
            __syncthreads();
        }
    }

    // ---- epilogue: store C ----
#pragma unroll
    for (int mt = 0; mt < 2; mt++) {
        int row0 = bm + wm * 32 + mt * 16 + grp;
#pragma unroll
        for (int nt = 0; nt < 8; nt++) {
            int col = bn + wn * 64 + nt * 8 + tig * 2;
            if (row0 < NN)
                *(float2*)&C[(size_t)row0 * DD + col] =
                    make_float2(cacc[mt][nt][0], cacc[mt][nt][1]);
            if (row0 + 8 < NN)
                *(float2*)&C[(size_t)(row0 + 8) * DD + col] =
                    make_float2(cacc[mt][nt][2], cacc[mt][nt][3]);
        }
    }
}

// ---------------- aggregation: hyperedge <- mean over incident nodes ------------
__global__ void edge_agg_k() {
    int gw = (blockIdx.x * blockDim.x + threadIdx.x) >> 5;
    int lane = threadIdx.x & 31;
    if (gw >= NE) return;
    int deg = g_deg_e[gw];
    if (deg > ELLS) deg = ELLS;
    float4 a0 = make_float4(0.f, 0.f, 0.f, 0.f);
    float4 a1 = a0;
    const int* __restrict__ idx = g_ell_he + (size_t)gw * ELLS;
    for (int k = 0; k < deg; k++) {
        int n = idx[k];
        const float4* row = (const float4*)(g_xw + (size_t)n * DD);
        float4 v0 = __ldg(&row[lane]);
        float4 v1 = __ldg(&row[lane + 32]);
        a0.x += v0.x; a0.y += v0.y; a0.z += v0.z; a0.w += v0.w;
        a1.x += v1.x; a1.y += v1.y; a1.z += v1.z; a1.w += v1.w;
    }
    float inv = (deg > 0) ? 1.f / (float)deg : 0.f;
    a0.x *= inv; a0.y *= inv; a0.z *= inv; a0.w *= inv;
    a1.x *= inv; a1.y *= inv; a1.z *= inv; a1.w *= inv;
    float4* orow = (float4*)(g_edge + (size_t)gw * DD);
    orow[lane] = a0;
    orow[lane + 32] = a1;
}

// ---------------- aggregation: node <- mean over incident hyperedges + epilogue -
__global__ void node_agg_k(const float* __restrict__ bias,
                           const float* __restrict__ prelu_a,
                           const float* __restrict__ residual,
                           float* __restrict__ out_ext,
                           int layer2) {
    int gw = (blockIdx.x * blockDim.x + threadIdx.x) >> 5;
    int lane = threadIdx.x & 31;
    if (gw >= NN) return;
    int deg = g_deg_n[gw];
    if (deg > ELLS) deg = ELLS;
    float4 a0 = make_float4(0.f, 0.f, 0.f, 0.f);
    float4 a1 = a0;
    const int* __restrict__ idx = g_ell_node + (size_t)gw * ELLS;
    for (int k = 0; k < deg; k++) {
        int h = idx[k];
        const float4* row = (const float4*)(g_edge + (size_t)h * DD);
        float4 v0 = __ldg(&row[lane]);
        float4 v1 = __ldg(&row[lane + 32]);
        a0.x += v0.x; a0.y += v0.y; a0.z += v0.z; a0.w += v0.w;
        a1.x += v1.x; a1.y += v1.y; a1.z += v1.z; a1.w += v1.w;
    }
    float inv = (deg > 0) ? 1.f / (float)deg : 0.f;
    float a = __ldg(prelu_a);
    float4 b0 = *(const float4*)&bias[lane * 4];
    float4 b1 = *(const float4*)&bias[128 + lane * 4];

    float4 r0, r1;
    r0.x = a0.x * inv + b0.x; r0.y = a0.y * inv + b0.y;
    r0.z = a0.z * inv + b0.z; r0.w = a0.w * inv + b0.w;
    r1.x = a1.x * inv + b1.x; r1.y = a1.y * inv + b1.y;
    r1.z = a1.z * inv + b1.z; r1.w = a1.w * inv + b1.w;

    if (layer2) {
        const float4* xr = (const float4*)(residual + (size_t)gw * DD);
        float4 x0 = __ldg(&xr[lane]);
        float4 x1 = __ldg(&xr[lane + 32]);
        r0.x += x0.x; r0.y += x0.y; r0.z += x0.z; r0.w += x0.w;
        r1.x += x1.x; r1.y += x1.y; r1.z += x1.z; r1.w += x1.w;
    }

    r0.x = (r0.x >= 0.f) ? r0.x : a * r0.x;
    r0.y = (r0.y >= 0.f) ? r0.y : a * r0.y;
    r0.z = (r0.z >= 0.f) ? r0.z : a * r0.z;
    r0.w = (r0.w >= 0.f) ? r0.w : a * r0.w;
    r1.x = (r1.x >= 0.f) ? r1.x : a * r1.x;
    r1.y = (r1.y >= 0.f) ? r1.y : a * r1.y;
    r1.z = (r1.z >= 0.f) ? r1.z : a * r1.z;
    r1.w = (r1.w >= 0.f) ? r1.w : a * r1.w;

    float* out = layer2 ? out_ext : (float*)g_h1;
    float4* orow = (float4*)(out + (size_t)gw * DD);
    orow[lane] = r0;
    orow[lane + 32] = r1;
}

// ---------------- launch ---------------------------------------------------------
extern "C" void kernel_launch(void* const* d_in, const int* in_sizes, int n_in,
                              void* d_out, int out_size) {
    const float* x   = (const float*)d_in[0];
    const float* W1  = (const float*)d_in[1];
    const float* b1  = (const float*)d_in[2];
    const float* W2  = (const float*)d_in[3];
    const float* b2  = (const float*)d_in[4];
    const float* pa  = (const float*)d_in[5];
    const void*  hei = d_in[6];
    float* out = (float*)d_out;

    // ELL incidence build (recomputed every launch; deterministic)
    init_k<<<(NN + 255) / 256, 256>>>();
    detect_k<<<1, 1024>>>((const unsigned long long*)hei);
    build_k<<<(EE + 255) / 256, 256>>>(hei);

    dim3 gg((NN + BM - 1) / BM, DD / BN);
    int agg_blocks = (NN * 32 + 255) / 256;   // one warp per row, 8 warps/block

    // layer 1: xw = x @ W1^T ; edge agg ; node agg (+b1, prelu) -> g_h1
    gemm_bf16_k<<<gg, 256>>>(x, W1, 0);
    edge_agg_k<<<agg_blocks, 256>>>();
    node_agg_k<<<agg_blocks, 256>>>(b1, pa, nullptr, nullptr, 0);

    // layer 2: xw = h1 @ W2^T ; edge agg ; node agg (+b2, +x residual, prelu)
    gemm_bf16_k<<<gg, 256>>>(x, W2, 1);
    edge_agg_k<<<agg_blocks, 256>>>();
    node_agg_k<<<agg_blocks, 256>>>(b2, pa, x, out, 1);
}